// round 3
// baseline (speedup 1.0000x reference)
#include <cuda_runtime.h>

// Problem constants
#define T_STEPS 2048
#define B_TOT   256
#define H_DIM   512
#define D_IN    529            // 16 (x) + 512 (h) + 1 (cost)
#define STRIDE  564            // padded row stride in floats (odd 16B-word stride -> conflict-friendly)
#define NW      141            // 16B words per row
#define WPT     35             // 16B words per j-chunk (4 chunks * 35 = 140 words >= 133 data words)
#define CHUNK   140            // floats per j-chunk
#define CTAS_PER_CL 8
#define B_PER_CL    16
#define ROWS_PER_CTA 64
#define NTHREADS 512

// ping-pong hidden-state buffers (L2 resident, 2MB total)
__device__ float g_hbuf[2][B_TOT * H_DIM];

__device__ __forceinline__ void ffma2(unsigned long long &d, unsigned long long a, unsigned long long b) {
    // packed dual fp32 FMA: d.lo += a.lo*b.lo ; d.hi += a.hi*b.hi
    asm("fma.rn.f32x2 %0, %1, %2, %0;" : "+l"(d) : "l"(a), "l"(b));
}

__device__ __forceinline__ float unpack_sum(unsigned long long v) {
    float lo = __uint_as_float((unsigned)(v & 0xffffffffull));
    float hi = __uint_as_float((unsigned)(v >> 32));
    return lo + hi;
}

extern "C" __global__ void __launch_bounds__(NTHREADS, 1) __cluster_dims__(CTAS_PER_CL, 1, 1)
rnn_scan_kernel(const float* __restrict__ x,       // [B, T, 16]
                const float* __restrict__ hidden,  // [B, 512]
                const float* __restrict__ cost,    // [B, T]
                const float* __restrict__ Wo,      // [1, 529]
                const float* __restrict__ Wh,      // [512, 529]
                float* __restrict__ out)           // [B*T] outs, then [B*512] h_final
{
    extern __shared__ float smem[];
    float* W_s  = smem;                                // 64 x 564
    float* in_s = smem + ROWS_PER_CTA * STRIDE;        // 16 x 564 : [x(16)|h(512)|c(1)|zeros]
    float* Wo_s = in_s + B_PER_CL * STRIDE;            // 564

    const int tid   = threadIdx.x;
    const int crank = blockIdx.x & (CTAS_PER_CL - 1);  // rank within cluster
    const int clid  = blockIdx.x >> 3;                 // cluster id (0..15)
    const int bbase = clid * B_PER_CL;                 // global batch base for this cluster
    const int row0  = crank * ROWS_PER_CTA;            // H rows owned by this CTA

    // ---- one-time: load W chunk (zero-padded), Wo, zero-pad in_s tails ----
    for (int idx = tid; idx < ROWS_PER_CTA * STRIDE; idx += NTHREADS) {
        int r = idx / STRIDE;
        int c = idx - r * STRIDE;
        W_s[idx] = (c < D_IN) ? Wh[(size_t)(row0 + r) * D_IN + c] : 0.0f;
    }
    for (int idx = tid; idx < STRIDE; idx += NTHREADS)
        Wo_s[idx] = (idx < D_IN) ? Wo[idx] : 0.0f;
    for (int z = tid; z < B_PER_CL * (STRIDE - D_IN); z += NTHREADS) {
        int b = z / (STRIDE - D_IN);
        int c = D_IN + (z - b * (STRIDE - D_IN));
        in_s[b * STRIDE + c] = 0.0f;
    }

    // ---- one-time: copy this CTA's 2 batch rows of hidden into g_hbuf[1] ----
    for (int idx = tid; idx < 2 * H_DIM; idx += NTHREADS) {
        int bl  = idx >> 9;          // 0..1
        int col = idx & (H_DIM - 1);
        size_t off = (size_t)(bbase + crank * 2 + bl) * H_DIM + col;
        g_hbuf[1][off] = hidden[off];
    }
    __syncthreads();
    asm volatile("barrier.cluster.arrive.aligned;" ::: "memory");
    asm volatile("barrier.cluster.wait.aligned;"   ::: "memory");

    // compute-phase thread mapping: jc (reduction split) | b4 (4-batch tile) | i2 (2-row tile)
    const int jc = tid & 3;          // j-chunk
    const int b4 = (tid >> 2) & 3;   // batch block of 4
    const int i2 = tid >> 4;         // output-row pair (0..31)

    // h staging mapping: one warp per batch row
    const int hb = tid >> 5;         // 0..15
    const int hq = tid & 31;

    // x/cost prefetch registers (valid for tid < 16)
    float4 xr0, xr1, xr2, xr3;
    float  cr = 0.0f;
    if (tid < B_PER_CL) {
        const float4* xp = (const float4*)(x + ((size_t)(bbase + tid) * T_STEPS + 0) * 16);
        xr0 = __ldg(xp + 0); xr1 = __ldg(xp + 1); xr2 = __ldg(xp + 2); xr3 = __ldg(xp + 3);
        cr  = __ldg(cost + (size_t)(bbase + tid) * T_STEPS + 0);
    }

    for (int t = 0; t < T_STEPS; ++t) {
        // ---- stage inter = [x_t | h | c_t] into in_s ----
        {
            const float4* hsrc = (const float4*)(g_hbuf[(t + 1) & 1] + (size_t)(bbase + hb) * H_DIM);
            float4* hdst = (float4*)(in_s + hb * STRIDE + 16);
            #pragma unroll
            for (int k = 0; k < 4; ++k)
                hdst[k * 32 + hq] = __ldcg(hsrc + k * 32 + hq);
        }
        if (tid < B_PER_CL) {
            float4* dx = (float4*)(in_s + tid * STRIDE);
            dx[0] = xr0; dx[1] = xr1; dx[2] = xr2; dx[3] = xr3;
            in_s[tid * STRIDE + 528] = cr;
        }
        __syncthreads();

        // ---- prefetch x/cost for step t+1 (DRAM latency hidden under compute) ----
        if (tid < B_PER_CL && t + 1 < T_STEPS) {
            const float4* xp = (const float4*)(x + ((size_t)(bbase + tid) * T_STEPS + (t + 1)) * 16);
            xr0 = __ldg(xp + 0); xr1 = __ldg(xp + 1); xr2 = __ldg(xp + 2); xr3 = __ldg(xp + 3);
            cr  = __ldg(cost + (size_t)(bbase + tid) * T_STEPS + (t + 1));
        }

        // ---- o_t = Wo . inter  (cluster CTA 0 only; uses pre-update h) ----
        if (crank == 0) {
            int b = tid >> 5, js = tid & 31;
            const ulonglong2* wop = (const ulonglong2*)Wo_s;
            const ulonglong2* hp  = (const ulonglong2*)(in_s + b * STRIDE);
            unsigned long long acc0 = 0ull;
            int w0 = js * 5;
            int w1 = min(NW, w0 + 5);
            for (int w = w0; w < w1; ++w) {
                ulonglong2 a = wop[w], h = hp[w];
                ffma2(acc0, a.x, h.x);
                ffma2(acc0, a.y, h.y);
            }
            float r = unpack_sum(acc0);
            r += __shfl_xor_sync(0xffffffffu, r, 1);
            r += __shfl_xor_sync(0xffffffffu, r, 2);
            r += __shfl_xor_sync(0xffffffffu, r, 4);
            r += __shfl_xor_sync(0xffffffffu, r, 8);
            r += __shfl_xor_sync(0xffffffffu, r, 16);
            if (js == 0) out[(size_t)(bbase + b) * T_STEPS + t] = r;
        }

        // ---- main matvec: h_new[b, i] = W[i,:] . inter[b,:]  (2i x 4b tile / thread) ----
        unsigned long long acc[2][4];
        #pragma unroll
        for (int a = 0; a < 2; ++a)
            #pragma unroll
            for (int c = 0; c < 4; ++c) acc[a][c] = 0ull;

        const float* wb  = W_s  + (i2 * 2) * STRIDE + jc * CHUNK;
        const float* hb2 = in_s + (b4 * 4) * STRIDE + jc * CHUNK;

        #pragma unroll 5
        for (int k = 0; k < WPT; ++k) {
            ulonglong2 wv[2], hv[4];
            #pragma unroll
            for (int a = 0; a < 2; ++a)
                wv[a] = *(const ulonglong2*)(wb + a * STRIDE + 4 * k);
            #pragma unroll
            for (int c = 0; c < 4; ++c)
                hv[c] = *(const ulonglong2*)(hb2 + c * STRIDE + 4 * k);
            #pragma unroll
            for (int a = 0; a < 2; ++a)
                #pragma unroll
                for (int c = 0; c < 4; ++c) {
                    ffma2(acc[a][c], wv[a].x, hv[c].x);
                    ffma2(acc[a][c], wv[a].y, hv[c].y);
                }
        }

        // ---- reduce across the 4 jc lanes (adjacent lanes) ----
        float rr[2][4];
        #pragma unroll
        for (int a = 0; a < 2; ++a)
            #pragma unroll
            for (int c = 0; c < 4; ++c) {
                float r = unpack_sum(acc[a][c]);
                r += __shfl_xor_sync(0xffffffffu, r, 1);
                r += __shfl_xor_sync(0xffffffffu, r, 2);
                rr[a][c] = r;
            }

        // ---- write h_new chunk (last step writes h_final region of out) ----
        if ((tid & 3) == 0) {
            float* hdst = (t == T_STEPS - 1) ? (out + (size_t)B_TOT * T_STEPS)
                                             : g_hbuf[t & 1];
            #pragma unroll
            for (int c = 0; c < 4; ++c) {
                int bl = b4 * 4 + c;
                float2 v = make_float2(rr[0][c], rr[1][c]);
                __stcg((float2*)(hdst + (size_t)(bbase + bl) * H_DIM + row0 + i2 * 2), v);
            }
        }

        // ---- cluster barrier: publish h_new (L2 via stcg) before next step reads ----
        asm volatile("barrier.cluster.arrive.aligned;" ::: "memory");
        asm volatile("barrier.cluster.wait.aligned;"   ::: "memory");
    }
}

extern "C" void kernel_launch(void* const* d_in, const int* in_sizes, int n_in,
                              void* d_out, int out_size) {
    const float* x      = (const float*)d_in[0];
    const float* hidden = (const float*)d_in[1];
    const float* cost   = (const float*)d_in[2];
    const float* Wo     = (const float*)d_in[3];
    const float* Wh     = (const float*)d_in[4];
    float* out = (float*)d_out;

    size_t smem = (size_t)(ROWS_PER_CTA * STRIDE + B_PER_CL * STRIDE + STRIDE) * sizeof(float);
    cudaFuncSetAttribute(rnn_scan_kernel, cudaFuncAttributeMaxDynamicSharedMemorySize, (int)smem);
    rnn_scan_kernel<<<128, NTHREADS, smem>>>(x, hidden, cost, Wo, Wh, out);
}

// round 4
// speedup vs baseline: 1.2822x; 1.2822x over previous
#include <cuda_runtime.h>

// Problem constants
#define T_STEPS 2048
#define B_TOT   256
#define H_DIM   512
#define D_IN    529            // 16 (x) + 512 (h) + 1 (cost)
#define STRIDE  544            // padded inter row stride (floats) = 8 slices * 68
#define SLICE   68             // floats per j-slice (17 x float4)
#define NW      136            // 16B words per inter row
#define CTAS_PER_CL 8
#define B_PER_CL    16
#define ROWS_PER_CTA 64
#define NTHREADS 512

// ping-pong hidden-state buffers (L2 resident, 2MB total)
__device__ float g_hbuf[2][B_TOT * H_DIM];

__device__ __forceinline__ void ffma2(unsigned long long &d, unsigned long long a, unsigned long long b) {
    // packed dual fp32 FMA: d.lo += a.lo*b.lo ; d.hi += a.hi*b.hi
    asm("fma.rn.f32x2 %0, %1, %2, %0;" : "+l"(d) : "l"(a), "l"(b));
}

__device__ __forceinline__ float unpack_sum(unsigned long long v) {
    float lo = __uint_as_float((unsigned)(v & 0xffffffffull));
    float hi = __uint_as_float((unsigned)(v >> 32));
    return lo + hi;
}

__device__ __forceinline__ unsigned long long packf2(float lo, float hi) {
    return ((unsigned long long)__float_as_uint(hi) << 32) | (unsigned long long)__float_as_uint(lo);
}

extern "C" __global__ void __launch_bounds__(NTHREADS, 1) __cluster_dims__(CTAS_PER_CL, 1, 1)
rnn_scan_kernel(const float* __restrict__ x,       // [B, T, 16]
                const float* __restrict__ hidden,  // [B, 512]
                const float* __restrict__ cost,    // [B, T]
                const float* __restrict__ Wo,      // [1, 529]
                const float* __restrict__ Wh,      // [512, 529]
                float* __restrict__ out)           // [B*T] outs, then [B*512] h_final
{
    extern __shared__ float smem[];
    float* in_s = smem;                         // 16 x 544 : [x(16)|h(512)|c(1)|zeros(15)]
    float* Wo_s = in_s + B_PER_CL * STRIDE;     // 544
    float* red  = Wo_s + STRIDE;                // 8 jc x 16 b x 64 r partials = 8192 floats

    const int tid   = threadIdx.x;
    const int lane  = tid & 31;
    const int w     = tid >> 5;                 // warp 0..15
    const int rh    = w & 1;                    // row half
    const int jc    = w >> 1;                   // j-slice 0..7
    const int r_loc = rh * 32 + lane;           // local output row 0..63

    const int crank = blockIdx.x & (CTAS_PER_CL - 1);
    const int clid  = blockIdx.x >> 3;
    const int bbase = clid * B_PER_CL;
    const int row0  = crank * ROWS_PER_CTA;

    // ---- one-time: load my W slice into registers (zero-padded to 544 cols) ----
    unsigned long long Wr[SLICE / 2];
    {
        const float* wrow = Wh + (size_t)(row0 + r_loc) * D_IN;
        #pragma unroll
        for (int k = 0; k < SLICE / 2; ++k) {
            int c0 = jc * SLICE + 2 * k;
            float lo = (c0     < D_IN) ? __ldg(wrow + c0)     : 0.0f;
            float hi = (c0 + 1 < D_IN) ? __ldg(wrow + c0 + 1) : 0.0f;
            Wr[k] = packf2(lo, hi);
        }
    }

    // ---- one-time: Wo padded, in_s tail zeros, hidden -> g_hbuf[1] ----
    for (int idx = tid; idx < STRIDE; idx += NTHREADS)
        Wo_s[idx] = (idx < D_IN) ? Wo[idx] : 0.0f;
    for (int z = tid; z < B_PER_CL * (STRIDE - D_IN); z += NTHREADS) {
        int b = z / (STRIDE - D_IN);
        int c = D_IN + (z - b * (STRIDE - D_IN));
        in_s[b * STRIDE + c] = 0.0f;
    }
    for (int idx = tid; idx < 2 * H_DIM; idx += NTHREADS) {
        int bl  = idx >> 9;
        int col = idx & (H_DIM - 1);
        size_t off = (size_t)(bbase + crank * 2 + bl) * H_DIM + col;
        g_hbuf[1][off] = hidden[off];
    }
    __syncthreads();
    asm volatile("barrier.cluster.arrive.aligned;" ::: "memory");
    asm volatile("barrier.cluster.wait.aligned;"   ::: "memory");

    // x/cost prefetch registers (valid for tid < 16)
    float4 xr0, xr1, xr2, xr3;
    float  cr = 0.0f;
    if (tid < B_PER_CL) {
        const float4* xp = (const float4*)(x + ((size_t)(bbase + tid) * T_STEPS) * 16);
        xr0 = __ldg(xp + 0); xr1 = __ldg(xp + 1); xr2 = __ldg(xp + 2); xr3 = __ldg(xp + 3);
        cr  = __ldg(cost + (size_t)(bbase + tid) * T_STEPS);
    }

    for (int t = 0; t < T_STEPS; ++t) {
        // ---- stage inter = [x_t | h | c_t] into in_s (warp w stages batch row w) ----
        {
            const float4* hsrc = (const float4*)(g_hbuf[(t + 1) & 1] + (size_t)(bbase + w) * H_DIM);
            float4* hdst = (float4*)(in_s + w * STRIDE + 16);
            #pragma unroll
            for (int k = 0; k < 4; ++k)
                hdst[k * 32 + lane] = __ldcg(hsrc + k * 32 + lane);
        }
        if (tid < B_PER_CL) {
            float4* dx = (float4*)(in_s + tid * STRIDE);
            dx[0] = xr0; dx[1] = xr1; dx[2] = xr2; dx[3] = xr3;
            in_s[tid * STRIDE + 528] = cr;
        }
        __syncthreads();

        // ---- prefetch x/cost for t+1 ----
        if (tid < B_PER_CL && t + 1 < T_STEPS) {
            const float4* xp = (const float4*)(x + ((size_t)(bbase + tid) * T_STEPS + (t + 1)) * 16);
            xr0 = __ldg(xp + 0); xr1 = __ldg(xp + 1); xr2 = __ldg(xp + 2); xr3 = __ldg(xp + 3);
            cr  = __ldg(cost + (size_t)(bbase + tid) * T_STEPS + (t + 1));
        }

        // ---- o_t = Wo . inter  (cluster CTA 0 only; pre-update h) ----
        if (crank == 0) {
            int b = w, js = lane;
            const ulonglong2* wop = (const ulonglong2*)Wo_s;
            const ulonglong2* hp  = (const ulonglong2*)(in_s + b * STRIDE);
            unsigned long long acc0 = 0ull;
            int w0 = js * 5;
            int w1 = min(NW, w0 + 5);
            for (int q = w0; q < w1; ++q) {
                ulonglong2 a = wop[q], h = hp[q];
                ffma2(acc0, a.x, h.x);
                ffma2(acc0, a.y, h.y);
            }
            float r = unpack_sum(acc0);
            r += __shfl_xor_sync(0xffffffffu, r, 1);
            r += __shfl_xor_sync(0xffffffffu, r, 2);
            r += __shfl_xor_sync(0xffffffffu, r, 4);
            r += __shfl_xor_sync(0xffffffffu, r, 8);
            r += __shfl_xor_sync(0xffffffffu, r, 16);
            if (js == 0) out[(size_t)(bbase + b) * T_STEPS + t] = r;
        }

        // ---- main matvec: W rows in regs, h broadcast from SMEM ----
        // thread -> (row r_loc, slice jc); 2 groups of 8 batches
        #pragma unroll
        for (int g = 0; g < 2; ++g) {
            unsigned long long acc[8];
            #pragma unroll
            for (int b = 0; b < 8; ++b) acc[b] = 0ull;

            const float* hbase = in_s + (g * 8) * STRIDE + jc * SLICE;
            #pragma unroll
            for (int kk = 0; kk < SLICE / 4; ++kk) {       // 17 x 16B chunks
                #pragma unroll
                for (int b = 0; b < 8; ++b) {
                    ulonglong2 hv = *(const ulonglong2*)(hbase + b * STRIDE + 4 * kk);
                    ffma2(acc[b], Wr[2 * kk],     hv.x);
                    ffma2(acc[b], Wr[2 * kk + 1], hv.y);
                }
            }
            #pragma unroll
            for (int b = 0; b < 8; ++b)
                red[(jc * 16 + g * 8 + b) * 64 + r_loc] = unpack_sum(acc[b]);
        }
        __syncthreads();

        // ---- reduce 8 jc partials, write h_new ----
        {
            float* hdst = (t == T_STEPS - 1) ? (out + (size_t)B_TOT * T_STEPS)
                                             : g_hbuf[t & 1];
            #pragma unroll
            for (int pp = 0; pp < 2; ++pp) {
                int p = tid + pp * NTHREADS;            // (b*64 + r), 0..1023
                float s = 0.0f;
                #pragma unroll
                for (int j = 0; j < 8; ++j) s += red[j * 1024 + p];
                int b = p >> 6, r = p & 63;
                __stcg(hdst + (size_t)(bbase + b) * H_DIM + row0 + r, s);
            }
        }

        // ---- cluster barrier: publish h_new before next step reads ----
        asm volatile("barrier.cluster.arrive.aligned;" ::: "memory");
        asm volatile("barrier.cluster.wait.aligned;"   ::: "memory");
    }
}

extern "C" void kernel_launch(void* const* d_in, const int* in_sizes, int n_in,
                              void* d_out, int out_size) {
    const float* x      = (const float*)d_in[0];
    const float* hidden = (const float*)d_in[1];
    const float* cost   = (const float*)d_in[2];
    const float* Wo     = (const float*)d_in[3];
    const float* Wh     = (const float*)d_in[4];
    float* out = (float*)d_out;

    size_t smem = (size_t)(B_PER_CL * STRIDE + STRIDE + 8 * 16 * 64) * sizeof(float);
    cudaFuncSetAttribute(rnn_scan_kernel, cudaFuncAttributeMaxDynamicSharedMemorySize, (int)smem);
    rnn_scan_kernel<<<128, NTHREADS, smem>>>(x, hidden, cost, Wo, Wh, out);
}

// round 5
// speedup vs baseline: 1.3411x; 1.0459x over previous
#include <cuda_runtime.h>

// Problem constants
#define T_STEPS 2048
#define B_TOT   256
#define H_DIM   512
#define D_IN    529            // 16 (x) + 512 (h) + 1 (cost)
#define STRIDE  544            // padded inter row stride (floats) = 8 slices * 68
#define SLICE   68             // floats per j-slice (17 x float4)
#define NW      136            // 16B words per inter row
#define CTAS_PER_CL 8
#define B_PER_CL    16
#define ROWS_PER_CTA 64
#define NTHREADS 512
#define XROW    20             // xc staging row: 16 x + 1 cost + pad

// ping-pong hidden-state buffers (L2 resident, 2MB total)
__device__ float g_hbuf[2][B_TOT * H_DIM];

__device__ __forceinline__ void ffma2(unsigned long long &d, unsigned long long a, unsigned long long b) {
    // packed dual fp32 FMA: d.lo += a.lo*b.lo ; d.hi += a.hi*b.hi
    asm("fma.rn.f32x2 %0, %1, %2, %0;" : "+l"(d) : "l"(a), "l"(b));
}

__device__ __forceinline__ float unpack_sum(unsigned long long v) {
    float lo = __uint_as_float((unsigned)(v & 0xffffffffull));
    float hi = __uint_as_float((unsigned)(v >> 32));
    return lo + hi;
}

__device__ __forceinline__ unsigned long long packf2(float lo, float hi) {
    return ((unsigned long long)__float_as_uint(hi) << 32) | (unsigned long long)__float_as_uint(lo);
}

extern "C" __global__ void __launch_bounds__(NTHREADS, 1) __cluster_dims__(CTAS_PER_CL, 1, 1)
rnn_scan_kernel(const float* __restrict__ x,       // [B, T, 16]
                const float* __restrict__ hidden,  // [B, 512]
                const float* __restrict__ cost,    // [B, T]
                const float* __restrict__ Wo,      // [1, 529]
                const float* __restrict__ Wh,      // [512, 529]
                float* __restrict__ out)           // [B*T] outs, then [B*512] h_final
{
    extern __shared__ float smem[];
    float* in_s = smem;                         // 16 x 544 : [x(16)|h(512)|c(1)|zeros(15)]
    float* Wo_s = in_s + B_PER_CL * STRIDE;     // 544
    float* red  = Wo_s + STRIDE;                // 8 jc x 16 b x 64 r partials = 8192 floats
    float* xc_s = red + 8 * B_PER_CL * ROWS_PER_CTA;  // 2 x 16 x 20 double buffer

    const int tid   = threadIdx.x;
    const int lane  = tid & 31;
    const int w     = tid >> 5;                 // warp 0..15
    const int rh    = w & 1;                    // row half
    const int jc    = w >> 1;                   // j-slice 0..7
    const int r_loc = rh * 32 + lane;           // local output row 0..63

    const int crank = blockIdx.x & (CTAS_PER_CL - 1);
    const int clid  = blockIdx.x >> 3;
    const int bbase = clid * B_PER_CL;
    const int row0  = crank * ROWS_PER_CTA;

    // ---- one-time: load my W slice into registers (zero-padded to 544 cols) ----
    unsigned long long Wr[SLICE / 2];
    {
        const float* wrow = Wh + (size_t)(row0 + r_loc) * D_IN;
        #pragma unroll
        for (int k = 0; k < SLICE / 2; ++k) {
            int c0 = jc * SLICE + 2 * k;
            float lo = (c0     < D_IN) ? __ldg(wrow + c0)     : 0.0f;
            float hi = (c0 + 1 < D_IN) ? __ldg(wrow + c0 + 1) : 0.0f;
            Wr[k] = packf2(lo, hi);
        }
    }

    // ---- one-time: Wo padded, in_s tail zeros, hidden -> g_hbuf[1], x/cost t=0 ----
    for (int idx = tid; idx < STRIDE; idx += NTHREADS)
        Wo_s[idx] = (idx < D_IN) ? Wo[idx] : 0.0f;
    for (int z = tid; z < B_PER_CL * (STRIDE - D_IN); z += NTHREADS) {
        int b = z / (STRIDE - D_IN);
        int c = D_IN + (z - b * (STRIDE - D_IN));
        in_s[b * STRIDE + c] = 0.0f;
    }
    for (int idx = tid; idx < 2 * H_DIM; idx += NTHREADS) {
        int bl  = idx >> 9;
        int col = idx & (H_DIM - 1);
        size_t off = (size_t)(bbase + crank * 2 + bl) * H_DIM + col;
        g_hbuf[1][off] = hidden[off];
    }
    if (tid < B_PER_CL) {
        const float* xp = x + ((size_t)(bbase + tid) * T_STEPS) * 16;
        #pragma unroll
        for (int q = 0; q < 16; ++q) xc_s[tid * XROW + q] = __ldg(xp + q);
        xc_s[tid * XROW + 16] = __ldg(cost + (size_t)(bbase + tid) * T_STEPS);
    }
    __syncthreads();
    asm volatile("barrier.cluster.arrive.aligned;" ::: "memory");
    asm volatile("barrier.cluster.wait.aligned;"   ::: "memory");

    for (int t = 0; t < T_STEPS; ++t) {
        const int cur = t & 1;
        // ---- stage inter = [x_t | h | c_t] into in_s (warp w stages batch row w) ----
        {
            const float4* hsrc = (const float4*)(g_hbuf[(t + 1) & 1] + (size_t)(bbase + w) * H_DIM);
            float4* hdst = (float4*)(in_s + w * STRIDE + 16);
            #pragma unroll
            for (int k = 0; k < 4; ++k)
                hdst[k * 32 + lane] = __ldcg(hsrc + k * 32 + lane);
        }
        if (tid < 256) {
            int b = tid >> 4, q = tid & 15;
            in_s[b * STRIDE + q] = xc_s[cur * B_PER_CL * XROW + b * XROW + q];
        } else if (tid < 256 + B_PER_CL) {
            int b = tid - 256;
            in_s[b * STRIDE + 528] = xc_s[cur * B_PER_CL * XROW + b * XROW + 16];
        }
        __syncthreads();

        // ---- prefetch x/cost for t+1 into the other xc buffer (transient regs) ----
        if (tid < B_PER_CL && t + 1 < T_STEPS) {
            float* dst = xc_s + ((t + 1) & 1) * B_PER_CL * XROW + tid * XROW;
            const float* xp = x + ((size_t)(bbase + tid) * T_STEPS + (t + 1)) * 16;
            #pragma unroll
            for (int q = 0; q < 16; ++q) dst[q] = __ldg(xp + q);
            dst[16] = __ldg(cost + (size_t)(bbase + tid) * T_STEPS + (t + 1));
        }

        // ---- o_t = Wo . inter  (cluster CTA 0 only; pre-update h) ----
        if (crank == 0) {
            int b = w, js = lane;
            const ulonglong2* wop = (const ulonglong2*)Wo_s;
            const ulonglong2* hp  = (const ulonglong2*)(in_s + b * STRIDE);
            unsigned long long acc0 = 0ull;
            int w0 = js * 5;
            int w1 = min(NW, w0 + 5);
            for (int q = w0; q < w1; ++q) {
                ulonglong2 a = wop[q], h = hp[q];
                ffma2(acc0, a.x, h.x);
                ffma2(acc0, a.y, h.y);
            }
            float r = unpack_sum(acc0);
            r += __shfl_xor_sync(0xffffffffu, r, 1);
            r += __shfl_xor_sync(0xffffffffu, r, 2);
            r += __shfl_xor_sync(0xffffffffu, r, 4);
            r += __shfl_xor_sync(0xffffffffu, r, 8);
            r += __shfl_xor_sync(0xffffffffu, r, 16);
            if (js == 0) out[(size_t)(bbase + b) * T_STEPS + t] = r;
        }

        // ---- main matvec: W rows in regs, h broadcast from SMEM ----
        // thread -> (row r_loc, slice jc); 4 groups of 4 batches (low reg pressure)
        #pragma unroll
        for (int g = 0; g < 4; ++g) {
            unsigned long long acc[4];
            #pragma unroll
            for (int b = 0; b < 4; ++b) acc[b] = 0ull;

            const float* hbase = in_s + (g * 4) * STRIDE + jc * SLICE;
            #pragma unroll
            for (int kk = 0; kk < SLICE / 4; ++kk) {       // 17 x 16B chunks
                #pragma unroll
                for (int b = 0; b < 4; ++b) {
                    ulonglong2 hv = *(const ulonglong2*)(hbase + b * STRIDE + 4 * kk);
                    ffma2(acc[b], Wr[2 * kk],     hv.x);
                    ffma2(acc[b], Wr[2 * kk + 1], hv.y);
                }
            }
            #pragma unroll
            for (int b = 0; b < 4; ++b)
                red[(jc * 16 + g * 4 + b) * 64 + r_loc] = unpack_sum(acc[b]);
        }
        __syncthreads();

        // ---- reduce 8 jc partials, write h_new ----
        {
            float* hdst = (t == T_STEPS - 1) ? (out + (size_t)B_TOT * T_STEPS)
                                             : g_hbuf[t & 1];
            #pragma unroll
            for (int pp = 0; pp < 2; ++pp) {
                int p = tid + pp * NTHREADS;            // (b*64 + r), 0..1023
                float s = 0.0f;
                #pragma unroll
                for (int j = 0; j < 8; ++j) s += red[j * 1024 + p];
                int b = p >> 6, r = p & 63;
                __stcg(hdst + (size_t)(bbase + b) * H_DIM + row0 + r, s);
            }
        }

        // ---- cluster barrier: publish h_new before next step reads ----
        asm volatile("barrier.cluster.arrive.aligned;" ::: "memory");
        asm volatile("barrier.cluster.wait.aligned;"   ::: "memory");
    }
}

extern "C" void kernel_launch(void* const* d_in, const int* in_sizes, int n_in,
                              void* d_out, int out_size) {
    const float* x      = (const float*)d_in[0];
    const float* hidden = (const float*)d_in[1];
    const float* cost   = (const float*)d_in[2];
    const float* Wo     = (const float*)d_in[3];
    const float* Wh     = (const float*)d_in[4];
    float* out = (float*)d_out;

    size_t smem = (size_t)(B_PER_CL * STRIDE + STRIDE + 8 * B_PER_CL * ROWS_PER_CTA
                           + 2 * B_PER_CL * XROW) * sizeof(float);
    cudaFuncSetAttribute(rnn_scan_kernel, cudaFuncAttributeMaxDynamicSharedMemorySize, (int)smem);
    rnn_scan_kernel<<<128, NTHREADS, smem>>>(x, hidden, cost, Wo, Wh, out);
}